// round 5
// baseline (speedup 1.0000x reference)
#include <cuda_runtime.h>
#include <cuda_bf16.h>
#include <cstdint>

// Problem constants: B=8, H=64, W=64, C=256, NUM_HEADS=8, KEY_DIM=32
#define M_TOT   32768
#define C_DIM   256
#define ELEMS   (M_TOT * C_DIM)   // 8388608

// ---------------- scratch (device globals; no allocation allowed) ----------
__device__ __align__(16) float g_q[ELEMS];
__device__ __align__(16) float g_k[ELEMS];
__device__ __align__(16) float g_v[ELEMS];
__device__ __align__(16) float g_lepe[ELEMS];
__device__ __align__(16) float g_v1[ELEMS];

__device__ __align__(16) __nv_bfloat16 g_ahi[ELEMS];
__device__ __align__(16) __nv_bfloat16 g_alo[ELEMS];
__device__ __align__(16) __nv_bfloat16 g_whi[4 * 65536];
__device__ __align__(16) __nv_bfloat16 g_wlo[4 * 65536];

// ---------------- helpers ---------------------------------------------------
__device__ __forceinline__ uint32_t smem_u32(const void* p) {
    uint32_t a;
    asm("{ .reg .u64 t; cvta.to.shared.u64 t, %1; cvt.u32.u64 %0, t; }"
        : "=r"(a) : "l"(p));
    return a;
}

__device__ __forceinline__ void mma16816(float* c, const uint32_t* a,
                                         uint32_t b0, uint32_t b1)
{
    asm volatile(
        "mma.sync.aligned.m16n8k16.row.col.f32.bf16.bf16.f32 "
        "{%0,%1,%2,%3}, {%4,%5,%6,%7}, {%8,%9}, {%0,%1,%2,%3};"
        : "+f"(c[0]), "+f"(c[1]), "+f"(c[2]), "+f"(c[3])
        : "r"(a[0]), "r"(a[1]), "r"(a[2]), "r"(a[3]), "r"(b0), "r"(b1));
}

__device__ __forceinline__ void ldm_x4(uint32_t* r, uint32_t addr) {
    asm volatile("ldmatrix.sync.aligned.m8n8.x4.shared.b16 {%0,%1,%2,%3}, [%4];"
        : "=r"(r[0]), "=r"(r[1]), "=r"(r[2]), "=r"(r[3]) : "r"(addr));
}

__device__ __forceinline__ void split4(const float* v, uint2& hp, uint2& lp) {
    uint32_t h[2], l[2];
#pragma unroll
    for (int q = 0; q < 2; q++) {
        __nv_bfloat16 h0 = __float2bfloat16(v[2 * q]);
        __nv_bfloat16 h1 = __float2bfloat16(v[2 * q + 1]);
        float r0 = v[2 * q]     - __bfloat162float(h0);
        float r1 = v[2 * q + 1] - __bfloat162float(h1);
        __nv_bfloat16 l0 = __float2bfloat16(r0);
        __nv_bfloat16 l1 = __float2bfloat16(r1);
        h[q] = (uint32_t)__bfloat16_as_ushort(h0) |
               ((uint32_t)__bfloat16_as_ushort(h1) << 16);
        l[q] = (uint32_t)__bfloat16_as_ushort(l0) |
               ((uint32_t)__bfloat16_as_ushort(l1) << 16);
    }
    hp = make_uint2(h[0], h[1]);
    lp = make_uint2(l[0], l[1]);
}

// ---------------------------------------------------------------------------
// Split x (fp32) into bf16 hi/lo.
// ---------------------------------------------------------------------------
__global__ __launch_bounds__(256)
void split_kernel(const float* __restrict__ a,
                  __nv_bfloat16* __restrict__ hi, __nv_bfloat16* __restrict__ lo,
                  int n4)
{
    int i = blockIdx.x * 256 + threadIdx.x;
    if (i >= n4) return;
    float4 v = ((const float4*)a)[i];
    float vv[4] = {v.x, v.y, v.z, v.w};
    uint2 hp, lp;
    split4(vv, hp, lp);
    ((uint2*)hi)[i] = hp;
    ((uint2*)lo)[i] = lp;
}

// Split all four 256x256 weight matrices in one launch (grid.y selects W).
__global__ __launch_bounds__(256)
void split_w_kernel(const float* __restrict__ W0, const float* __restrict__ W1,
                    const float* __restrict__ W2, const float* __restrict__ W3,
                    __nv_bfloat16* __restrict__ hi, __nv_bfloat16* __restrict__ lo)
{
    const int w = blockIdx.y;
    const float* W = (w == 0) ? W0 : (w == 1) ? W1 : (w == 2) ? W2 : W3;
    const int i = blockIdx.x * 256 + threadIdx.x;   // 0..16383
    float4 v = ((const float4*)W)[i];
    float vv[4] = {v.x, v.y, v.z, v.w};
    uint2 hp, lp;
    split4(vv, hp, lp);
    ((uint2*)hi)[w * 16384 + i] = hp;
    ((uint2*)lo)[w * 16384 + i] = lp;
}

// ---------------------------------------------------------------------------
// HMMA GEMM, fp32 emulation (hi/lo bf16, 3 products), cp.async double buffer.
// CTA tile 128x128, 512 threads = 16 warps (4m x 4n), warp tile 32x32.
// grid.z selects which output (QKV fused launch); smem row stride 80 B.
// ---------------------------------------------------------------------------
#define TILE_B  10240         // 128 * 80
#define STAGE_B (4 * TILE_B)  // Ah, Al, Bh, Bl
#define GEMM_SMEM (2 * STAGE_B)

__global__ __launch_bounds__(512)
void gemm_hmma(const __nv_bfloat16* __restrict__ Ahi,
               const __nv_bfloat16* __restrict__ Alo,
               const __nv_bfloat16* __restrict__ Whi,
               const __nv_bfloat16* __restrict__ Wlo,
               const float* __restrict__ bias0, const float* __restrict__ bias1,
               const float* __restrict__ bias2,
               float* __restrict__ out0, float* __restrict__ out1,
               float* __restrict__ out2,
               float sc0, float sc1, float sc2)
{
    extern __shared__ __align__(16) char gsm[];

    const int z = blockIdx.z;
    const __nv_bfloat16* Bhi = Whi + z * 65536;
    const __nv_bfloat16* Blo = Wlo + z * 65536;
    const float* bias = (z == 0) ? bias0 : (z == 1) ? bias1 : bias2;
    float* out        = (z == 0) ? out0  : (z == 1) ? out1  : out2;
    const float scale = (z == 0) ? sc0   : (z == 1) ? sc1   : sc2;

    const int tid  = threadIdx.x;
    const int lane = tid & 31;
    const int warp = tid >> 5;
    const int wm   = warp >> 2;   // 0..3
    const int wn   = warp & 3;    // 0..3
    const int m0   = blockIdx.y * 128;
    const int n0   = blockIdx.x * 128;
    const int gid  = lane >> 2;
    const int tig  = lane & 3;

    float acc[2][4][4];
#pragma unroll
    for (int i = 0; i < 2; i++)
#pragma unroll
        for (int j = 0; j < 4; j++)
#pragma unroll
            for (int t = 0; t < 4; t++) acc[i][j][t] = 0.f;

    const uint4* gsrc[4] = { (const uint4*)Ahi + (size_t)m0 * 32,
                             (const uint4*)Alo + (size_t)m0 * 32,
                             (const uint4*)Bhi + (size_t)n0 * 32,
                             (const uint4*)Blo + (size_t)n0 * 32 };
    const uint32_t smem_base = smem_u32(gsm);

    const int lr = tid >> 2;      // 0..127
    const int lq = tid & 3;       // 0..3

    auto issue = [&](int chunk, int stg) {
        const int kq4 = chunk * 4;
        const uint32_t sb = smem_base + stg * STAGE_B;
#pragma unroll
        for (int tl = 0; tl < 4; tl++) {
            const uint4* src = gsrc[tl] + (size_t)lr * 32 + kq4 + lq;
            const uint32_t dst = sb + tl * TILE_B + lr * 80 + lq * 16;
            asm volatile("cp.async.ca.shared.global [%0], [%1], 16;"
                         :: "r"(dst), "l"(src));
        }
    };

    issue(0, 0);
    asm volatile("cp.async.commit_group;" ::: "memory");

    for (int c = 0; c < 8; c++) {
        if (c + 1 < 8) issue(c + 1, (c + 1) & 1);
        asm volatile("cp.async.commit_group;" ::: "memory");
        asm volatile("cp.async.wait_group 1;" ::: "memory");
        __syncthreads();

        const uint32_t sb = smem_base + (c & 1) * STAGE_B;
        const uint32_t sAh = sb, sAl = sb + TILE_B;
        const uint32_t sBh = sb + 2 * TILE_B, sBl = sb + 3 * TILE_B;

#pragma unroll
        for (int ks = 0; ks < 2; ks++) {
            const int kb = ks * 16;
            uint32_t ah[2][4], al[2][4];
            const int arow = wm * 32 + (lane & 15);
            const int acol = kb + ((lane >> 4) << 3);
#pragma unroll
            for (int i = 0; i < 2; i++) {
                const uint32_t off = (uint32_t)((arow + i * 16) * 80 + acol * 2);
                ldm_x4(ah[i], sAh + off);
                ldm_x4(al[i], sAl + off);
            }
            const int brow0 = wn * 32 + ((lane >> 4) & 1) * 8 + (lane & 7);
            const int bcol  = kb + ((lane >> 3) & 1) * 8;
#pragma unroll
            for (int jp = 0; jp < 2; jp++) {
                uint32_t bh[4], bl[4];
                const uint32_t off = (uint32_t)((brow0 + jp * 16) * 80 + bcol * 2);
                ldm_x4(bh, sBh + off);
                ldm_x4(bl, sBl + off);
#pragma unroll
                for (int jj = 0; jj < 2; jj++) {
                    const int j = jp * 2 + jj;
#pragma unroll
                    for (int i = 0; i < 2; i++) {
                        mma16816(acc[i][j], ah[i], bh[jj * 2], bh[jj * 2 + 1]);
                        mma16816(acc[i][j], al[i], bh[jj * 2], bh[jj * 2 + 1]);
                        mma16816(acc[i][j], ah[i], bl[jj * 2], bl[jj * 2 + 1]);
                    }
                }
            }
        }
        __syncthreads();
    }

    // Epilogue
#pragma unroll
    for (int i = 0; i < 2; i++) {
        const int row = m0 + wm * 32 + i * 16 + gid;
#pragma unroll
        for (int j = 0; j < 4; j++) {
            const int col = n0 + wn * 32 + j * 8 + tig * 2;
            const float b0 = bias[col], b1 = bias[col + 1];
            float2 v0 = make_float2((acc[i][j][0] + b0) * scale,
                                    (acc[i][j][1] + b1) * scale);
            float2 v1 = make_float2((acc[i][j][2] + b0) * scale,
                                    (acc[i][j][3] + b1) * scale);
            *(float2*)(out + (size_t)row * 256 + col)       = v0;
            *(float2*)(out + (size_t)(row + 8) * 256 + col) = v1;
        }
    }
}

// ---------------------------------------------------------------------------
// LePE: 5x5 depthwise conv, register-blocked 4 x-outputs per thread.
// ---------------------------------------------------------------------------
__global__ __launch_bounds__(256)
void lepe_kernel(const float* __restrict__ V,
                 const float* __restrict__ Wl,
                 const float* __restrict__ bl,
                 float* __restrict__ out)
{
    const int idx = blockIdx.x * 256 + threadIdx.x;
    const int c  = idx & 255;
    const int xg = (idx >> 8) & 15;
    const int y  = (idx >> 12) & 63;
    const int b  = idx >> 18;
    const int x0 = xg * 4;

    float w[5][5];
#pragma unroll
    for (int dy = 0; dy < 5; dy++)
#pragma unroll
        for (int dx = 0; dx < 5; dx++)
            w[dy][dx] = Wl[(dy * 5 + dx) * 256 + c];

    const float bias = bl[c];
    float acc[4] = {bias, bias, bias, bias};

#pragma unroll
    for (int dy = 0; dy < 5; dy++) {
        const int yy = y + dy - 2;
        if (yy < 0 || yy > 63) continue;
        const float* vrow = V + (size_t)(((b << 6) + yy) << 6) * 256 + c;
#pragma unroll
        for (int e = 0; e < 8; e++) {
            const int xx = x0 - 2 + e;
            if (xx < 0 || xx > 63) continue;
            const float val = vrow[(size_t)xx * 256];
#pragma unroll
            for (int u = 0; u < 4; u++) {
                const int dxi = e - u;
                if (dxi >= 0 && dxi < 5) acc[u] += val * w[dy][dxi];
            }
        }
    }

    float* orow = out + (size_t)((((b << 6) + y) << 6) + x0) * 256 + c;
#pragma unroll
    for (int u = 0; u < 4; u++) orow[(size_t)u * 256] = acc[u];
}

// ---------------------------------------------------------------------------
// Axis attention (fp32): 64x64x32 per (b, line, head).
// FUSE_OUT: add LePE and write bf16 hi/lo split (for final projection input);
// otherwise write fp32 (intermediate v1).
// ---------------------------------------------------------------------------
template <bool FUSE_OUT>
__global__ __launch_bounds__(64)
void attn_kernel(const float* __restrict__ Q,
                 const float* __restrict__ K,
                 const float* __restrict__ V,
                 const float* __restrict__ mask,
                 const float* __restrict__ lepe,
                 float* __restrict__ outf,
                 __nv_bfloat16* __restrict__ ohi,
                 __nv_bfloat16* __restrict__ olo,
                 int y_stride, int row_stride)
{
    __shared__ float4 sK[64][8];
    __shared__ float4 sV[64][8];
    __shared__ float  sS[64][65];

    const int n = blockIdx.x;
    const int y = blockIdx.y;
    const int b = blockIdx.z;
    const int t = threadIdx.x;

    const size_t base = (size_t)b * (64 * 64 * 256) + (size_t)y * y_stride + n * 32;

    for (int i = t; i < 512; i += 64) {
        const int r = i >> 3, j = i & 7;
        sK[r][j] = *((const float4*)(K + base + (size_t)r * row_stride) + j);
        sV[r][j] = *((const float4*)(V + base + (size_t)r * row_stride) + j);
    }

    float4 q[8];
    {
        const float4* qp = (const float4*)(Q + base + (size_t)t * row_stride);
#pragma unroll
        for (int j = 0; j < 8; j++) q[j] = qp[j];
    }
    __syncthreads();

#pragma unroll 4
    for (int k = 0; k < 64; k++) {
        float s = 0.f;
#pragma unroll
        for (int j = 0; j < 8; j++) {
            const float4 kv = sK[k][j];
            s += q[j].x * kv.x + q[j].y * kv.y + q[j].z * kv.z + q[j].w * kv.w;
        }
        sS[t][k] = s;
    }

    const float4* mrow = (const float4*)(mask + ((size_t)((n << 6) + t)) * 64);
    float mx = -1e30f;
#pragma unroll
    for (int j = 0; j < 16; j++) {
        const float4 m = mrow[j];
        float s0 = sS[t][4 * j + 0] + m.x;
        float s1 = sS[t][4 * j + 1] + m.y;
        float s2 = sS[t][4 * j + 2] + m.z;
        float s3 = sS[t][4 * j + 3] + m.w;
        sS[t][4 * j + 0] = s0; sS[t][4 * j + 1] = s1;
        sS[t][4 * j + 2] = s2; sS[t][4 * j + 3] = s3;
        mx = fmaxf(mx, fmaxf(fmaxf(s0, s1), fmaxf(s2, s3)));
    }

    float sum = 0.f;
#pragma unroll 8
    for (int k = 0; k < 64; k++) {
        const float e = __expf(sS[t][k] - mx);
        sS[t][k] = e;
        sum += e;
    }
    const float inv = 1.f / sum;

    float4 o[8];
#pragma unroll
    for (int j = 0; j < 8; j++) o[j] = make_float4(0.f, 0.f, 0.f, 0.f);

#pragma unroll 2
    for (int k = 0; k < 64; k++) {
        const float p = sS[t][k] * inv;
#pragma unroll
        for (int j = 0; j < 8; j++) {
            const float4 vv = sV[k][j];
            o[j].x += p * vv.x; o[j].y += p * vv.y;
            o[j].z += p * vv.z; o[j].w += p * vv.w;
        }
    }

    const size_t obase = base + (size_t)t * row_stride;
    if (!FUSE_OUT) {
        float4* op = (float4*)(outf + obase);
#pragma unroll
        for (int j = 0; j < 8; j++) op[j] = o[j];
    } else {
        const float4* lp4 = (const float4*)(lepe + obase);
#pragma unroll
        for (int j = 0; j < 8; j++) {
            const float4 lv = lp4[j];
            float vv[4] = {o[j].x + lv.x, o[j].y + lv.y,
                           o[j].z + lv.z, o[j].w + lv.w};
            uint2 hp, lpk;
            split4(vv, hp, lpk);
            *(uint2*)(ohi + obase + j * 4) = hp;
            *(uint2*)(olo + obase + j * 4) = lpk;
        }
    }
}

// ---------------------------------------------------------------------------
extern "C" void kernel_launch(void* const* d_in, const int* in_sizes, int n_in,
                              void* d_out, int out_size)
{
    const float* x      = (const float*)d_in[0];
    const float* mask_h = (const float*)d_in[1];
    const float* mask_w = (const float*)d_in[2];
    const float* Wq = (const float*)d_in[3];
    const float* bq = (const float*)d_in[4];
    const float* Wk = (const float*)d_in[5];
    const float* bk = (const float*)d_in[6];
    const float* Wv = (const float*)d_in[7];
    const float* bv = (const float*)d_in[8];
    const float* Wl = (const float*)d_in[9];
    const float* bl = (const float*)d_in[10];
    const float* Wo = (const float*)d_in[11];
    const float* bo = (const float*)d_in[12];
    float* out = (float*)d_out;

    float *q, *k, *v, *lepe, *v1;
    __nv_bfloat16 *ahi, *alo, *whi, *wlo;
    cudaGetSymbolAddress((void**)&q,    g_q);
    cudaGetSymbolAddress((void**)&k,    g_k);
    cudaGetSymbolAddress((void**)&v,    g_v);
    cudaGetSymbolAddress((void**)&lepe, g_lepe);
    cudaGetSymbolAddress((void**)&v1,   g_v1);
    cudaGetSymbolAddress((void**)&ahi,  g_ahi);
    cudaGetSymbolAddress((void**)&alo,  g_alo);
    cudaGetSymbolAddress((void**)&whi,  g_whi);
    cudaGetSymbolAddress((void**)&wlo,  g_wlo);

    static int smem_set = 0;
    if (!smem_set) {
        cudaFuncSetAttribute(gemm_hmma,
                             cudaFuncAttributeMaxDynamicSharedMemorySize,
                             GEMM_SMEM);
        smem_set = 1;
    }

    const float scaling = 0.17677669529663687f;  // 32^-0.5

    // Splits
    split_kernel<<<ELEMS / 4 / 256, 256>>>(x, ahi, alo, ELEMS / 4);
    split_w_kernel<<<dim3(64, 4), 256>>>(Wq, Wk, Wv, Wo, whi, wlo);

    // Fused QKV projection: grid.z selects output
    gemm_hmma<<<dim3(2, 256, 3), 512, GEMM_SMEM>>>(
        ahi, alo, whi, wlo, bq, bk, bv, q, k, v, 1.0f, scaling, 1.0f);

    lepe_kernel<<<ELEMS / 4 / 256, 256>>>(v, Wl, bl, lepe);

    dim3 attn_grid(8, 64, 8);
    // Width-axis attention -> v1 (fp32)
    attn_kernel<false><<<attn_grid, 64>>>(q, k, v, mask_w, nullptr,
                                          v1, nullptr, nullptr,
                                          /*y_stride=*/64 * 256, /*row_stride=*/256);
    // Height-axis attention + LePE add + hi/lo split fused
    attn_kernel<true><<<attn_grid, 64>>>(q, k, v1, mask_h, lepe,
                                         nullptr, ahi, alo,
                                         /*y_stride=*/256, /*row_stride=*/64 * 256);

    // Output projection
    gemm_hmma<<<dim3(2, 256, 1), 512, GEMM_SMEM>>>(
        ahi, alo, whi + 3 * 65536, wlo + 3 * 65536, bo, bo, bo,
        out, out, out, 1.0f, 1.0f, 1.0f);
}

// round 6
// speedup vs baseline: 1.0193x; 1.0193x over previous
#include <cuda_runtime.h>
#include <cuda_bf16.h>
#include <cstdint>

// Problem constants: B=8, H=64, W=64, C=256, NUM_HEADS=8, KEY_DIM=32
#define M_TOT   32768
#define C_DIM   256
#define ELEMS   (M_TOT * C_DIM)   // 8388608

// ---------------- scratch (device globals; no allocation allowed) ----------
__device__ __align__(16) float g_q[ELEMS];
__device__ __align__(16) float g_k[ELEMS];
__device__ __align__(16) float g_v[ELEMS];
__device__ __align__(16) float g_lepe[ELEMS];
__device__ __align__(16) float g_v1[ELEMS];

__device__ __align__(16) __nv_bfloat16 g_ahi[ELEMS];
__device__ __align__(16) __nv_bfloat16 g_alo[ELEMS];
__device__ __align__(16) __nv_bfloat16 g_whi[4 * 65536];
__device__ __align__(16) __nv_bfloat16 g_wlo[4 * 65536];

// ---------------- helpers ---------------------------------------------------
__device__ __forceinline__ uint32_t smem_u32(const void* p) {
    uint32_t a;
    asm("{ .reg .u64 t; cvta.to.shared.u64 t, %1; cvt.u32.u64 %0, t; }"
        : "=r"(a) : "l"(p));
    return a;
}

__device__ __forceinline__ void mma16816(float* c, const uint32_t* a,
                                         uint32_t b0, uint32_t b1)
{
    asm volatile(
        "mma.sync.aligned.m16n8k16.row.col.f32.bf16.bf16.f32 "
        "{%0,%1,%2,%3}, {%4,%5,%6,%7}, {%8,%9}, {%0,%1,%2,%3};"
        : "+f"(c[0]), "+f"(c[1]), "+f"(c[2]), "+f"(c[3])
        : "r"(a[0]), "r"(a[1]), "r"(a[2]), "r"(a[3]), "r"(b0), "r"(b1));
}

__device__ __forceinline__ void ldm_x4(uint32_t* r, uint32_t addr) {
    asm volatile("ldmatrix.sync.aligned.m8n8.x4.shared.b16 {%0,%1,%2,%3}, [%4];"
        : "=r"(r[0]), "=r"(r[1]), "=r"(r[2]), "=r"(r[3]) : "r"(addr));
}

__device__ __forceinline__ void split4(const float* v, uint2& hp, uint2& lp) {
    uint32_t h[2], l[2];
#pragma unroll
    for (int q = 0; q < 2; q++) {
        __nv_bfloat16 h0 = __float2bfloat16(v[2 * q]);
        __nv_bfloat16 h1 = __float2bfloat16(v[2 * q + 1]);
        float r0 = v[2 * q]     - __bfloat162float(h0);
        float r1 = v[2 * q + 1] - __bfloat162float(h1);
        __nv_bfloat16 l0 = __float2bfloat16(r0);
        __nv_bfloat16 l1 = __float2bfloat16(r1);
        h[q] = (uint32_t)__bfloat16_as_ushort(h0) |
               ((uint32_t)__bfloat16_as_ushort(h1) << 16);
        l[q] = (uint32_t)__bfloat16_as_ushort(l0) |
               ((uint32_t)__bfloat16_as_ushort(l1) << 16);
    }
    hp = make_uint2(h[0], h[1]);
    lp = make_uint2(l[0], l[1]);
}

// ---------------------------------------------------------------------------
// Split x (fp32) into bf16 hi/lo.
// ---------------------------------------------------------------------------
__global__ __launch_bounds__(256)
void split_kernel(const float* __restrict__ a,
                  __nv_bfloat16* __restrict__ hi, __nv_bfloat16* __restrict__ lo,
                  int n4)
{
    int i = blockIdx.x * 256 + threadIdx.x;
    if (i >= n4) return;
    float4 v = ((const float4*)a)[i];
    float vv[4] = {v.x, v.y, v.z, v.w};
    uint2 hp, lp;
    split4(vv, hp, lp);
    ((uint2*)hi)[i] = hp;
    ((uint2*)lo)[i] = lp;
}

// Split all four 256x256 weight matrices in one launch (grid.y selects W).
__global__ __launch_bounds__(256)
void split_w_kernel(const float* __restrict__ W0, const float* __restrict__ W1,
                    const float* __restrict__ W2, const float* __restrict__ W3,
                    __nv_bfloat16* __restrict__ hi, __nv_bfloat16* __restrict__ lo)
{
    const int w = blockIdx.y;
    const float* W = (w == 0) ? W0 : (w == 1) ? W1 : (w == 2) ? W2 : W3;
    const int i = blockIdx.x * 256 + threadIdx.x;   // 0..16383
    float4 v = ((const float4*)W)[i];
    float vv[4] = {v.x, v.y, v.z, v.w};
    uint2 hp, lp;
    split4(vv, hp, lp);
    ((uint2*)hi)[w * 16384 + i] = hp;
    ((uint2*)lo)[w * 16384 + i] = lp;
}

// ---------------------------------------------------------------------------
// HMMA GEMM, fp32 emulation (hi/lo bf16, 3 products), cp.async double buffer.
// CTA tile 128x256 (FULL N: A panel read exactly once).
// 512 threads = 16 warps (4m x 4n), warp tile 32x64. K chunk 32, 2 stages.
// Smem layout per stage: Ah[128x32] Al[128x32] Bh[256x32] Bl[256x32],
// all with row stride 80 B.
// ---------------------------------------------------------------------------
#define A_TILE_B  10240        // 128 * 80
#define B_TILE_B  20480        // 256 * 80
#define STAGE_B   (2 * A_TILE_B + 2 * B_TILE_B)   // 61440
#define GEMM_SMEM (2 * STAGE_B)                   // 122880

__global__ __launch_bounds__(512)
void gemm_hmma(const __nv_bfloat16* __restrict__ Ahi,
               const __nv_bfloat16* __restrict__ Alo,
               const __nv_bfloat16* __restrict__ Whi,
               const __nv_bfloat16* __restrict__ Wlo,
               const float* __restrict__ bias0, const float* __restrict__ bias1,
               const float* __restrict__ bias2,
               float* __restrict__ out0, float* __restrict__ out1,
               float* __restrict__ out2,
               float sc0, float sc1, float sc2)
{
    extern __shared__ __align__(16) char gsm[];

    const int z = blockIdx.z;
    const __nv_bfloat16* Bhi = Whi + z * 65536;
    const __nv_bfloat16* Blo = Wlo + z * 65536;
    const float* bias = (z == 0) ? bias0 : (z == 1) ? bias1 : bias2;
    float* out        = (z == 0) ? out0  : (z == 1) ? out1  : out2;
    const float scale = (z == 0) ? sc0   : (z == 1) ? sc1   : sc2;

    const int tid  = threadIdx.x;
    const int lane = tid & 31;
    const int warp = tid >> 5;
    const int wm   = warp >> 2;   // 0..3  (32-row slice)
    const int wn   = warp & 3;    // 0..3  (64-col slice)
    const int m0   = blockIdx.y * 128;
    const int gid  = lane >> 2;
    const int tig  = lane & 3;

    float acc[2][8][4];
#pragma unroll
    for (int i = 0; i < 2; i++)
#pragma unroll
        for (int j = 0; j < 8; j++)
#pragma unroll
            for (int t = 0; t < 4; t++) acc[i][j][t] = 0.f;

    const uint4* gAh = (const uint4*)Ahi + (size_t)m0 * 32;
    const uint4* gAl = (const uint4*)Alo + (size_t)m0 * 32;
    const uint4* gBh = (const uint4*)Bhi;
    const uint4* gBl = (const uint4*)Blo;
    const uint32_t smem_base = smem_u32(gsm);

    // cp.async one K-chunk (32 cols) into a stage: 6 x 16B per thread.
    auto issue = [&](int chunk, int stg) {
        const int kq4 = chunk * 4;
        const uint32_t sb = smem_base + stg * STAGE_B;
        {
            const int r = tid >> 2, q = tid & 3;   // A tiles: 512 ops each
            const uint32_t off = (uint32_t)(r * 80 + q * 16);
            asm volatile("cp.async.ca.shared.global [%0], [%1], 16;"
                         :: "r"(sb + off),
                            "l"(gAh + (size_t)r * 32 + kq4 + q));
            asm volatile("cp.async.ca.shared.global [%0], [%1], 16;"
                         :: "r"(sb + A_TILE_B + off),
                            "l"(gAl + (size_t)r * 32 + kq4 + q));
        }
#pragma unroll
        for (int rep = 0; rep < 2; rep++) {        // B tiles: 1024 ops each
            const int li = rep * 512 + tid;
            const int r = li >> 2, q = li & 3;
            const uint32_t off = (uint32_t)(r * 80 + q * 16);
            asm volatile("cp.async.ca.shared.global [%0], [%1], 16;"
                         :: "r"(sb + 2 * A_TILE_B + off),
                            "l"(gBh + (size_t)r * 32 + kq4 + q));
            asm volatile("cp.async.ca.shared.global [%0], [%1], 16;"
                         :: "r"(sb + 2 * A_TILE_B + B_TILE_B + off),
                            "l"(gBl + (size_t)r * 32 + kq4 + q));
        }
    };

    issue(0, 0);
    asm volatile("cp.async.commit_group;" ::: "memory");

    for (int c = 0; c < 8; c++) {
        if (c + 1 < 8) issue(c + 1, (c + 1) & 1);
        asm volatile("cp.async.commit_group;" ::: "memory");
        asm volatile("cp.async.wait_group 1;" ::: "memory");
        __syncthreads();

        const uint32_t sb  = smem_base + (c & 1) * STAGE_B;
        const uint32_t sAh = sb, sAl = sb + A_TILE_B;
        const uint32_t sBh = sb + 2 * A_TILE_B;
        const uint32_t sBl = sb + 2 * A_TILE_B + B_TILE_B;

#pragma unroll
        for (int ks = 0; ks < 2; ks++) {
            const int kb = ks * 16;
            uint32_t ah[2][4], al[2][4];
            const int arow = wm * 32 + (lane & 15);
            const int acol = kb + ((lane >> 4) << 3);
#pragma unroll
            for (int i = 0; i < 2; i++) {
                const uint32_t off = (uint32_t)((arow + i * 16) * 80 + acol * 2);
                ldm_x4(ah[i], sAh + off);
                ldm_x4(al[i], sAl + off);
            }
            const int brow0 = wn * 64 + ((lane >> 4) & 1) * 8 + (lane & 7);
            const int bcol  = kb + ((lane >> 3) & 1) * 8;
#pragma unroll
            for (int jp = 0; jp < 4; jp++) {
                uint32_t bh[4], bl[4];
                const uint32_t off = (uint32_t)((brow0 + jp * 16) * 80 + bcol * 2);
                ldm_x4(bh, sBh + off);
                ldm_x4(bl, sBl + off);
#pragma unroll
                for (int jj = 0; jj < 2; jj++) {
                    const int j = jp * 2 + jj;
#pragma unroll
                    for (int i = 0; i < 2; i++) {
                        mma16816(acc[i][j], ah[i], bh[jj * 2], bh[jj * 2 + 1]);
                        mma16816(acc[i][j], al[i], bh[jj * 2], bh[jj * 2 + 1]);
                        mma16816(acc[i][j], ah[i], bl[jj * 2], bl[jj * 2 + 1]);
                    }
                }
            }
        }
        __syncthreads();
    }

    // Epilogue
#pragma unroll
    for (int i = 0; i < 2; i++) {
        const int row = m0 + wm * 32 + i * 16 + gid;
#pragma unroll
        for (int j = 0; j < 8; j++) {
            const int col = wn * 64 + j * 8 + tig * 2;
            const float b0 = bias[col], b1 = bias[col + 1];
            float2 v0 = make_float2((acc[i][j][0] + b0) * scale,
                                    (acc[i][j][1] + b1) * scale);
            float2 v1 = make_float2((acc[i][j][2] + b0) * scale,
                                    (acc[i][j][3] + b1) * scale);
            *(float2*)(out + (size_t)row * 256 + col)       = v0;
            *(float2*)(out + (size_t)(row + 8) * 256 + col) = v1;
        }
    }
}

// ---------------------------------------------------------------------------
// LePE: 5x5 depthwise conv, register-blocked 4 x-outputs per thread.
// ---------------------------------------------------------------------------
__global__ __launch_bounds__(256)
void lepe_kernel(const float* __restrict__ V,
                 const float* __restrict__ Wl,
                 const float* __restrict__ bl,
                 float* __restrict__ out)
{
    const int idx = blockIdx.x * 256 + threadIdx.x;
    const int c  = idx & 255;
    const int xg = (idx >> 8) & 15;
    const int y  = (idx >> 12) & 63;
    const int b  = idx >> 18;
    const int x0 = xg * 4;

    float w[5][5];
#pragma unroll
    for (int dy = 0; dy < 5; dy++)
#pragma unroll
        for (int dx = 0; dx < 5; dx++)
            w[dy][dx] = Wl[(dy * 5 + dx) * 256 + c];

    const float bias = bl[c];
    float acc[4] = {bias, bias, bias, bias};

#pragma unroll
    for (int dy = 0; dy < 5; dy++) {
        const int yy = y + dy - 2;
        if (yy < 0 || yy > 63) continue;
        const float* vrow = V + (size_t)(((b << 6) + yy) << 6) * 256 + c;
#pragma unroll
        for (int e = 0; e < 8; e++) {
            const int xx = x0 - 2 + e;
            if (xx < 0 || xx > 63) continue;
            const float val = vrow[(size_t)xx * 256];
#pragma unroll
            for (int u = 0; u < 4; u++) {
                const int dxi = e - u;
                if (dxi >= 0 && dxi < 5) acc[u] += val * w[dy][dxi];
            }
        }
    }

    float* orow = out + (size_t)((((b << 6) + y) << 6) + x0) * 256 + c;
#pragma unroll
    for (int u = 0; u < 4; u++) orow[(size_t)u * 256] = acc[u];
}

// ---------------------------------------------------------------------------
// Axis attention (fp32): 64x64x32 per (b, line, head).
// FUSE_OUT: add LePE and write bf16 hi/lo split (for final projection input).
// ---------------------------------------------------------------------------
template <bool FUSE_OUT>
__global__ __launch_bounds__(64)
void attn_kernel(const float* __restrict__ Q,
                 const float* __restrict__ K,
                 const float* __restrict__ V,
                 const float* __restrict__ mask,
                 const float* __restrict__ lepe,
                 float* __restrict__ outf,
                 __nv_bfloat16* __restrict__ ohi,
                 __nv_bfloat16* __restrict__ olo,
                 int y_stride, int row_stride)
{
    __shared__ float4 sK[64][8];
    __shared__ float4 sV[64][8];
    __shared__ float  sS[64][65];

    const int n = blockIdx.x;
    const int y = blockIdx.y;
    const int b = blockIdx.z;
    const int t = threadIdx.x;

    const size_t base = (size_t)b * (64 * 64 * 256) + (size_t)y * y_stride + n * 32;

    for (int i = t; i < 512; i += 64) {
        const int r = i >> 3, j = i & 7;
        sK[r][j] = *((const float4*)(K + base + (size_t)r * row_stride) + j);
        sV[r][j] = *((const float4*)(V + base + (size_t)r * row_stride) + j);
    }

    float4 q[8];
    {
        const float4* qp = (const float4*)(Q + base + (size_t)t * row_stride);
#pragma unroll
        for (int j = 0; j < 8; j++) q[j] = qp[j];
    }
    __syncthreads();

#pragma unroll 4
    for (int k = 0; k < 64; k++) {
        float s = 0.f;
#pragma unroll
        for (int j = 0; j < 8; j++) {
            const float4 kv = sK[k][j];
            s += q[j].x * kv.x + q[j].y * kv.y + q[j].z * kv.z + q[j].w * kv.w;
        }
        sS[t][k] = s;
    }

    const float4* mrow = (const float4*)(mask + ((size_t)((n << 6) + t)) * 64);
    float mx = -1e30f;
#pragma unroll
    for (int j = 0; j < 16; j++) {
        const float4 m = mrow[j];
        float s0 = sS[t][4 * j + 0] + m.x;
        float s1 = sS[t][4 * j + 1] + m.y;
        float s2 = sS[t][4 * j + 2] + m.z;
        float s3 = sS[t][4 * j + 3] + m.w;
        sS[t][4 * j + 0] = s0; sS[t][4 * j + 1] = s1;
        sS[t][4 * j + 2] = s2; sS[t][4 * j + 3] = s3;
        mx = fmaxf(mx, fmaxf(fmaxf(s0, s1), fmaxf(s2, s3)));
    }

    float sum = 0.f;
#pragma unroll 8
    for (int k = 0; k < 64; k++) {
        const float e = __expf(sS[t][k] - mx);
        sS[t][k] = e;
        sum += e;
    }
    const float inv = 1.f / sum;

    float4 o[8];
#pragma unroll
    for (int j = 0; j < 8; j++) o[j] = make_float4(0.f, 0.f, 0.f, 0.f);

#pragma unroll 2
    for (int k = 0; k < 64; k++) {
        const float p = sS[t][k] * inv;
#pragma unroll
        for (int j = 0; j < 8; j++) {
            const float4 vv = sV[k][j];
            o[j].x += p * vv.x; o[j].y += p * vv.y;
            o[j].z += p * vv.z; o[j].w += p * vv.w;
        }
    }

    const size_t obase = base + (size_t)t * row_stride;
    if (!FUSE_OUT) {
        float4* op = (float4*)(outf + obase);
#pragma unroll
        for (int j = 0; j < 8; j++) op[j] = o[j];
    } else {
        const float4* lp4 = (const float4*)(lepe + obase);
#pragma unroll
        for (int j = 0; j < 8; j++) {
            const float4 lv = lp4[j];
            float vv[4] = {o[j].x + lv.x, o[j].y + lv.y,
                           o[j].z + lv.z, o[j].w + lv.w};
            uint2 hp, lpk;
            split4(vv, hp, lpk);
            *(uint2*)(ohi + obase + j * 4) = hp;
            *(uint2*)(olo + obase + j * 4) = lpk;
        }
    }
}

// ---------------------------------------------------------------------------
extern "C" void kernel_launch(void* const* d_in, const int* in_sizes, int n_in,
                              void* d_out, int out_size)
{
    const float* x      = (const float*)d_in[0];
    const float* mask_h = (const float*)d_in[1];
    const float* mask_w = (const float*)d_in[2];
    const float* Wq = (const float*)d_in[3];
    const float* bq = (const float*)d_in[4];
    const float* Wk = (const float*)d_in[5];
    const float* bk = (const float*)d_in[6];
    const float* Wv = (const float*)d_in[7];
    const float* bv = (const float*)d_in[8];
    const float* Wl = (const float*)d_in[9];
    const float* bl = (const float*)d_in[10];
    const float* Wo = (const float*)d_in[11];
    const float* bo = (const float*)d_in[12];
    float* out = (float*)d_out;

    float *q, *k, *v, *lepe, *v1;
    __nv_bfloat16 *ahi, *alo, *whi, *wlo;
    cudaGetSymbolAddress((void**)&q,    g_q);
    cudaGetSymbolAddress((void**)&k,    g_k);
    cudaGetSymbolAddress((void**)&v,    g_v);
    cudaGetSymbolAddress((void**)&lepe, g_lepe);
    cudaGetSymbolAddress((void**)&v1,   g_v1);
    cudaGetSymbolAddress((void**)&ahi,  g_ahi);
    cudaGetSymbolAddress((void**)&alo,  g_alo);
    cudaGetSymbolAddress((void**)&whi,  g_whi);
    cudaGetSymbolAddress((void**)&wlo,  g_wlo);

    static int smem_set = 0;
    if (!smem_set) {
        cudaFuncSetAttribute(gemm_hmma,
                             cudaFuncAttributeMaxDynamicSharedMemorySize,
                             GEMM_SMEM);
        smem_set = 1;
    }

    const float scaling = 0.17677669529663687f;  // 32^-0.5

    // Splits
    split_kernel<<<ELEMS / 4 / 256, 256>>>(x, ahi, alo, ELEMS / 4);
    split_w_kernel<<<dim3(64, 4), 256>>>(Wq, Wk, Wv, Wo, whi, wlo);

    // Fused QKV projection: grid.z selects weight/output; full-N CTA tiles.
    gemm_hmma<<<dim3(1, 256, 3), 512, GEMM_SMEM>>>(
        ahi, alo, whi, wlo, bq, bk, bv, q, k, v, 1.0f, scaling, 1.0f);

    lepe_kernel<<<ELEMS / 4 / 256, 256>>>(v, Wl, bl, lepe);

    dim3 attn_grid(8, 64, 8);
    // Width-axis attention -> v1 (fp32)
    attn_kernel<false><<<attn_grid, 64>>>(q, k, v, mask_w, nullptr,
                                          v1, nullptr, nullptr,
                                          /*y_stride=*/64 * 256, /*row_stride=*/256);
    // Height-axis attention + LePE add + hi/lo split fused
    attn_kernel<true><<<attn_grid, 64>>>(q, k, v1, mask_h, lepe,
                                         nullptr, ahi, alo,
                                         /*y_stride=*/256, /*row_stride=*/64 * 256);

    // Output projection
    gemm_hmma<<<dim3(1, 256, 1), 512, GEMM_SMEM>>>(
        ahi, alo, whi + 3 * 65536, wlo + 3 * 65536, bo, bo, bo,
        out, out, out, 1.0f, 1.0f, 1.0f);
}

// round 7
// speedup vs baseline: 1.3525x; 1.3269x over previous
#include <cuda_runtime.h>
#include <cuda_bf16.h>
#include <cstdint>

// Problem constants: B=8, H=64, W=64, C=256, NUM_HEADS=8, KEY_DIM=32
#define M_TOT   32768
#define C_DIM   256
#define ELEMS   (M_TOT * C_DIM)   // 8388608

// ---------------- scratch (device globals; no allocation allowed) ----------
__device__ __align__(16) float g_v[ELEMS];
__device__ __align__(16) float g_lepe[ELEMS];

__device__ __align__(16) __nv_bfloat16 g_qhi[ELEMS];
__device__ __align__(16) __nv_bfloat16 g_qlo[ELEMS];
__device__ __align__(16) __nv_bfloat16 g_khi[ELEMS];
__device__ __align__(16) __nv_bfloat16 g_klo[ELEMS];
__device__ __align__(16) __nv_bfloat16 g_vhi[ELEMS];
__device__ __align__(16) __nv_bfloat16 g_vlo[ELEMS];
__device__ __align__(16) __nv_bfloat16 g_v1hi[ELEMS];
__device__ __align__(16) __nv_bfloat16 g_v1lo[ELEMS];
__device__ __align__(16) __nv_bfloat16 g_ahi[ELEMS];
__device__ __align__(16) __nv_bfloat16 g_alo[ELEMS];
__device__ __align__(16) __nv_bfloat16 g_whi[4 * 65536];
__device__ __align__(16) __nv_bfloat16 g_wlo[4 * 65536];

// ---------------- helpers ---------------------------------------------------
__device__ __forceinline__ uint32_t smem_u32(const void* p) {
    uint32_t a;
    asm("{ .reg .u64 t; cvta.to.shared.u64 t, %1; cvt.u32.u64 %0, t; }"
        : "=r"(a) : "l"(p));
    return a;
}

__device__ __forceinline__ void mma16816(float* c, const uint32_t* a,
                                         uint32_t b0, uint32_t b1)
{
    asm volatile(
        "mma.sync.aligned.m16n8k16.row.col.f32.bf16.bf16.f32 "
        "{%0,%1,%2,%3}, {%4,%5,%6,%7}, {%8,%9}, {%0,%1,%2,%3};"
        : "+f"(c[0]), "+f"(c[1]), "+f"(c[2]), "+f"(c[3])
        : "r"(a[0]), "r"(a[1]), "r"(a[2]), "r"(a[3]), "r"(b0), "r"(b1));
}

__device__ __forceinline__ void ldm_x4(uint32_t* r, uint32_t addr) {
    asm volatile("ldmatrix.sync.aligned.m8n8.x4.shared.b16 {%0,%1,%2,%3}, [%4];"
        : "=r"(r[0]), "=r"(r[1]), "=r"(r[2]), "=r"(r[3]) : "r"(addr));
}

__device__ __forceinline__ void ldm_x2t(uint32_t* r, uint32_t addr) {
    asm volatile("ldmatrix.sync.aligned.m8n8.x2.trans.shared.b16 {%0,%1}, [%2];"
        : "=r"(r[0]), "=r"(r[1]) : "r"(addr));
}

// Split pair (x0 -> low 16, x1 -> high 16) into bf16 hi word; residual lo word.
__device__ __forceinline__ uint32_t packsplit(float x0, float x1, uint32_t& lo) {
    __nv_bfloat16 h0 = __float2bfloat16(x0), h1 = __float2bfloat16(x1);
    float r0 = x0 - __bfloat162float(h0);
    float r1 = x1 - __bfloat162float(h1);
    __nv_bfloat16 l0 = __float2bfloat16(r0), l1 = __float2bfloat16(r1);
    lo = (uint32_t)__bfloat16_as_ushort(l0) |
         ((uint32_t)__bfloat16_as_ushort(l1) << 16);
    return (uint32_t)__bfloat16_as_ushort(h0) |
           ((uint32_t)__bfloat16_as_ushort(h1) << 16);
}

// ---------------------------------------------------------------------------
// Split x (fp32) into bf16 hi/lo.
// ---------------------------------------------------------------------------
__global__ __launch_bounds__(256)
void split_kernel(const float* __restrict__ a,
                  __nv_bfloat16* __restrict__ hi, __nv_bfloat16* __restrict__ lo,
                  int n4)
{
    int i = blockIdx.x * 256 + threadIdx.x;
    if (i >= n4) return;
    float4 v = ((const float4*)a)[i];
    uint32_t l0, l1;
    uint32_t h0 = packsplit(v.x, v.y, l0);
    uint32_t h1 = packsplit(v.z, v.w, l1);
    ((uint2*)hi)[i] = make_uint2(h0, h1);
    ((uint2*)lo)[i] = make_uint2(l0, l1);
}

// Split all four 256x256 weight matrices in one launch (grid.y selects W).
__global__ __launch_bounds__(256)
void split_w_kernel(const float* __restrict__ W0, const float* __restrict__ W1,
                    const float* __restrict__ W2, const float* __restrict__ W3,
                    __nv_bfloat16* __restrict__ hi, __nv_bfloat16* __restrict__ lo)
{
    const int w = blockIdx.y;
    const float* W = (w == 0) ? W0 : (w == 1) ? W1 : (w == 2) ? W2 : W3;
    const int i = blockIdx.x * 256 + threadIdx.x;   // 0..16383
    float4 v = ((const float4*)W)[i];
    uint32_t l0, l1;
    uint32_t h0 = packsplit(v.x, v.y, l0);
    uint32_t h1 = packsplit(v.z, v.w, l1);
    ((uint2*)hi)[w * 16384 + i] = make_uint2(h0, h1);
    ((uint2*)lo)[w * 16384 + i] = make_uint2(l0, l1);
}

// ---------------------------------------------------------------------------
// HMMA GEMM, fp32 emulation (hi/lo bf16, 3 products), cp.async double buffer.
// CTA tile 128x256 (full N), 512 threads = 16 warps (4m x 4n), warp tile 32x64.
// Epilogue: optionally write bf16 hi/lo split output and/or fp32 output.
// ---------------------------------------------------------------------------
#define A_TILE_B  10240        // 128 * 80
#define B_TILE_B  20480        // 256 * 80
#define STAGE_B   (2 * A_TILE_B + 2 * B_TILE_B)   // 61440
#define GEMM_SMEM (2 * STAGE_B)                   // 122880

__global__ __launch_bounds__(512)
void gemm_hmma(const __nv_bfloat16* __restrict__ Ahi,
               const __nv_bfloat16* __restrict__ Alo,
               const __nv_bfloat16* __restrict__ Whi,
               const __nv_bfloat16* __restrict__ Wlo,
               const float* __restrict__ bias0, const float* __restrict__ bias1,
               const float* __restrict__ bias2,
               __nv_bfloat16* __restrict__ h0, __nv_bfloat16* __restrict__ l0p,
               __nv_bfloat16* __restrict__ h1, __nv_bfloat16* __restrict__ l1p,
               __nv_bfloat16* __restrict__ h2, __nv_bfloat16* __restrict__ l2p,
               float* __restrict__ f2,     // fp32 out for z==2 (v)
               float* __restrict__ fout,   // if set: fp32-only output (out proj)
               float sc0, float sc1, float sc2)
{
    extern __shared__ __align__(16) char gsm[];

    const int z = blockIdx.z;
    const __nv_bfloat16* Bhi = Whi + z * 65536;
    const __nv_bfloat16* Blo = Wlo + z * 65536;
    const float* bias = (z == 0) ? bias0 : (z == 1) ? bias1 : bias2;
    const float scale = (z == 0) ? sc0   : (z == 1) ? sc1   : sc2;

    __nv_bfloat16 *ohi, *olo;
    float* of;
    if (fout) { of = fout; ohi = nullptr; olo = nullptr; }
    else {
        ohi = (z == 0) ? h0 : (z == 1) ? h1 : h2;
        olo = (z == 0) ? l0p : (z == 1) ? l1p : l2p;
        of  = (z == 2) ? f2 : nullptr;
    }

    const int tid  = threadIdx.x;
    const int lane = tid & 31;
    const int warp = tid >> 5;
    const int wm   = warp >> 2;
    const int wn   = warp & 3;
    const int m0   = blockIdx.y * 128;
    const int gid  = lane >> 2;
    const int tig  = lane & 3;

    float acc[2][8][4];
#pragma unroll
    for (int i = 0; i < 2; i++)
#pragma unroll
        for (int j = 0; j < 8; j++)
#pragma unroll
            for (int t = 0; t < 4; t++) acc[i][j][t] = 0.f;

    const uint4* gAh = (const uint4*)Ahi + (size_t)m0 * 32;
    const uint4* gAl = (const uint4*)Alo + (size_t)m0 * 32;
    const uint4* gBh = (const uint4*)Bhi;
    const uint4* gBl = (const uint4*)Blo;
    const uint32_t smem_base = smem_u32(gsm);

    auto issue = [&](int chunk, int stg) {
        const int kq4 = chunk * 4;
        const uint32_t sb = smem_base + stg * STAGE_B;
        {
            const int r = tid >> 2, q = tid & 3;
            const uint32_t off = (uint32_t)(r * 80 + q * 16);
            asm volatile("cp.async.ca.shared.global [%0], [%1], 16;"
                         :: "r"(sb + off),
                            "l"(gAh + (size_t)r * 32 + kq4 + q));
            asm volatile("cp.async.ca.shared.global [%0], [%1], 16;"
                         :: "r"(sb + A_TILE_B + off),
                            "l"(gAl + (size_t)r * 32 + kq4 + q));
        }
#pragma unroll
        for (int rep = 0; rep < 2; rep++) {
            const int li = rep * 512 + tid;
            const int r = li >> 2, q = li & 3;
            const uint32_t off = (uint32_t)(r * 80 + q * 16);
            asm volatile("cp.async.ca.shared.global [%0], [%1], 16;"
                         :: "r"(sb + 2 * A_TILE_B + off),
                            "l"(gBh + (size_t)r * 32 + kq4 + q));
            asm volatile("cp.async.ca.shared.global [%0], [%1], 16;"
                         :: "r"(sb + 2 * A_TILE_B + B_TILE_B + off),
                            "l"(gBl + (size_t)r * 32 + kq4 + q));
        }
    };

    issue(0, 0);
    asm volatile("cp.async.commit_group;" ::: "memory");

    for (int c = 0; c < 8; c++) {
        if (c + 1 < 8) issue(c + 1, (c + 1) & 1);
        asm volatile("cp.async.commit_group;" ::: "memory");
        asm volatile("cp.async.wait_group 1;" ::: "memory");
        __syncthreads();

        const uint32_t sb  = smem_base + (c & 1) * STAGE_B;
        const uint32_t sAh = sb, sAl = sb + A_TILE_B;
        const uint32_t sBh = sb + 2 * A_TILE_B;
        const uint32_t sBl = sb + 2 * A_TILE_B + B_TILE_B;

#pragma unroll
        for (int ks = 0; ks < 2; ks++) {
            const int kb = ks * 16;
            uint32_t ah[2][4], al[2][4];
            const int arow = wm * 32 + (lane & 15);
            const int acol = kb + ((lane >> 4) << 3);
#pragma unroll
            for (int i = 0; i < 2; i++) {
                const uint32_t off = (uint32_t)((arow + i * 16) * 80 + acol * 2);
                ldm_x4(ah[i], sAh + off);
                ldm_x4(al[i], sAl + off);
            }
            const int brow0 = wn * 64 + ((lane >> 4) & 1) * 8 + (lane & 7);
            const int bcol  = kb + ((lane >> 3) & 1) * 8;
#pragma unroll
            for (int jp = 0; jp < 4; jp++) {
                uint32_t bh[4], bl[4];
                const uint32_t off = (uint32_t)((brow0 + jp * 16) * 80 + bcol * 2);
                ldm_x4(bh, sBh + off);
                ldm_x4(bl, sBl + off);
#pragma unroll
                for (int jj = 0; jj < 2; jj++) {
                    const int j = jp * 2 + jj;
#pragma unroll
                    for (int i = 0; i < 2; i++) {
                        mma16816(acc[i][j], ah[i], bh[jj * 2], bh[jj * 2 + 1]);
                        mma16816(acc[i][j], al[i], bh[jj * 2], bh[jj * 2 + 1]);
                        mma16816(acc[i][j], ah[i], bl[jj * 2], bl[jj * 2 + 1]);
                    }
                }
            }
        }
        __syncthreads();
    }

    // Epilogue
#pragma unroll
    for (int i = 0; i < 2; i++) {
        const int row = m0 + wm * 32 + i * 16 + gid;
#pragma unroll
        for (int j = 0; j < 8; j++) {
            const int col = wn * 64 + j * 8 + tig * 2;
            const float b0 = bias[col], b1 = bias[col + 1];
            const float x0 = (acc[i][j][0] + b0) * scale;
            const float x1 = (acc[i][j][1] + b1) * scale;
            const float y0 = (acc[i][j][2] + b0) * scale;
            const float y1 = (acc[i][j][3] + b1) * scale;
            const size_t o0 = (size_t)row * 256 + col;
            const size_t o1 = o0 + 8 * 256;
            if (ohi) {
                uint32_t lo;
                uint32_t hi = packsplit(x0, x1, lo);
                *(uint32_t*)(ohi + o0) = hi;
                *(uint32_t*)(olo + o0) = lo;
                hi = packsplit(y0, y1, lo);
                *(uint32_t*)(ohi + o1) = hi;
                *(uint32_t*)(olo + o1) = lo;
            }
            if (of) {
                *(float2*)(of + o0) = make_float2(x0, x1);
                *(float2*)(of + o1) = make_float2(y0, y1);
            }
        }
    }
}

// ---------------------------------------------------------------------------
// LePE: 5x5 depthwise conv, register-blocked 4 x-outputs per thread.
// ---------------------------------------------------------------------------
__global__ __launch_bounds__(256)
void lepe_kernel(const float* __restrict__ V,
                 const float* __restrict__ Wl,
                 const float* __restrict__ bl,
                 float* __restrict__ out)
{
    const int idx = blockIdx.x * 256 + threadIdx.x;
    const int c  = idx & 255;
    const int xg = (idx >> 8) & 15;
    const int y  = (idx >> 12) & 63;
    const int b  = idx >> 18;
    const int x0 = xg * 4;

    float w[5][5];
#pragma unroll
    for (int dy = 0; dy < 5; dy++)
#pragma unroll
        for (int dx = 0; dx < 5; dx++)
            w[dy][dx] = Wl[(dy * 5 + dx) * 256 + c];

    const float bias = bl[c];
    float acc[4] = {bias, bias, bias, bias};

#pragma unroll
    for (int dy = 0; dy < 5; dy++) {
        const int yy = y + dy - 2;
        if (yy < 0 || yy > 63) continue;
        const float* vrow = V + (size_t)(((b << 6) + yy) << 6) * 256 + c;
#pragma unroll
        for (int e = 0; e < 8; e++) {
            const int xx = x0 - 2 + e;
            if (xx < 0 || xx > 63) continue;
            const float val = vrow[(size_t)xx * 256];
#pragma unroll
            for (int u = 0; u < 4; u++) {
                const int dxi = e - u;
                if (dxi >= 0 && dxi < 5) acc[u] += val * w[dy][dxi];
            }
        }
    }

    float* orow = out + (size_t)((((b << 6) + y) << 6) + x0) * 256 + c;
#pragma unroll
    for (int u = 0; u < 4; u++) orow[(size_t)u * 256] = acc[u];
}

// ---------------------------------------------------------------------------
// HMMA axis attention: one (b, line, head) 64x64x32 problem per block.
// 128 threads = 4 warps; warp w owns query rows 16w..16w+15.
// QK^T and PV on tensor cores with bf16 hi/lo fp32 emulation.
// FUSE: add LePE and write bf16 hi/lo for the output projection input.
// ---------------------------------------------------------------------------
template <bool FUSE>
__global__ __launch_bounds__(128)
void attn_hmma(const __nv_bfloat16* __restrict__ Qhi, const __nv_bfloat16* __restrict__ Qlo,
               const __nv_bfloat16* __restrict__ Khi, const __nv_bfloat16* __restrict__ Klo,
               const __nv_bfloat16* __restrict__ Vhi, const __nv_bfloat16* __restrict__ Vlo,
               const float* __restrict__ mask,
               const float* __restrict__ lepe,
               __nv_bfloat16* __restrict__ Ohi, __nv_bfloat16* __restrict__ Olo,
               int y_stride, int row_stride)
{
    __shared__ __align__(16) __nv_bfloat16 sQh[64][40];
    __shared__ __align__(16) __nv_bfloat16 sQl[64][40];
    __shared__ __align__(16) __nv_bfloat16 sKh[64][40];
    __shared__ __align__(16) __nv_bfloat16 sKl[64][40];
    __shared__ __align__(16) __nv_bfloat16 sVh[64][40];
    __shared__ __align__(16) __nv_bfloat16 sVl[64][40];

    const int n = blockIdx.x;
    const int y = blockIdx.y;
    const int b = blockIdx.z;
    const int tid  = threadIdx.x;
    const int lane = tid & 31;
    const int w    = tid >> 5;
    const int gid  = lane >> 2;
    const int tig  = lane & 3;

    const size_t base = (size_t)b * (64 * 64 * 256) + (size_t)y * y_stride + n * 32;

    // Stage Q/K/V hi/lo tiles (64 rows x 32 bf16 each; 80B smem rows).
    for (int i = tid; i < 256; i += 128) {
        const int r = i >> 2, c8 = (i & 3) * 8;
        const size_t g = base + (size_t)r * row_stride + c8;
        *(uint4*)&sQh[r][c8] = *(const uint4*)(Qhi + g);
        *(uint4*)&sQl[r][c8] = *(const uint4*)(Qlo + g);
        *(uint4*)&sKh[r][c8] = *(const uint4*)(Khi + g);
        *(uint4*)&sKl[r][c8] = *(const uint4*)(Klo + g);
        *(uint4*)&sVh[r][c8] = *(const uint4*)(Vhi + g);
        *(uint4*)&sVl[r][c8] = *(const uint4*)(Vlo + g);
    }
    __syncthreads();

    // Q fragments: m16k16 x 2 k-chunks.
    uint32_t qh[2][4], ql[2][4];
    {
        const int arow = 16 * w + (lane & 15);
        const int acol = (lane >> 4) << 3;
#pragma unroll
        for (int kc = 0; kc < 2; kc++) {
            ldm_x4(qh[kc], smem_u32(&sQh[arow][kc * 16 + acol]));
            ldm_x4(ql[kc], smem_u32(&sQl[arow][kc * 16 + acol]));
        }
    }

    // S = Q K^T (+ emulation), 8 n8-tiles.
    float sacc[8][4];
#pragma unroll
    for (int j = 0; j < 8; j++)
#pragma unroll
        for (int t = 0; t < 4; t++) sacc[j][t] = 0.f;

    {
        const int krow = ((lane >> 4) & 1) * 8 + (lane & 7);
        const int kcol = ((lane >> 3) & 1) * 8;
#pragma unroll
        for (int kc = 0; kc < 2; kc++)
#pragma unroll
            for (int jp = 0; jp < 4; jp++) {
                uint32_t kh[4], kl[4];
                ldm_x4(kh, smem_u32(&sKh[16 * jp + krow][kc * 16 + kcol]));
                ldm_x4(kl, smem_u32(&sKl[16 * jp + krow][kc * 16 + kcol]));
#pragma unroll
                for (int jj = 0; jj < 2; jj++) {
                    const int j = jp * 2 + jj;
                    mma16816(sacc[j], qh[kc], kh[jj * 2], kh[jj * 2 + 1]);
                    mma16816(sacc[j], ql[kc], kh[jj * 2], kh[jj * 2 + 1]);
                    mma16816(sacc[j], qh[kc], kl[jj * 2], kl[jj * 2 + 1]);
                }
            }
    }

    // Mask add + softmax on fragments (rows r0=16w+gid, r1=r0+8).
    const int r0 = 16 * w + gid;
    const int r1 = r0 + 8;
    const float* mbase = mask + (size_t)n * 4096;
    float mx0 = -1e30f, mx1 = -1e30f;
#pragma unroll
    for (int j = 0; j < 8; j++) {
        const float2 m0 = *(const float2*)(mbase + r0 * 64 + j * 8 + tig * 2);
        const float2 m1 = *(const float2*)(mbase + r1 * 64 + j * 8 + tig * 2);
        sacc[j][0] += m0.x; sacc[j][1] += m0.y;
        sacc[j][2] += m1.x; sacc[j][3] += m1.y;
        mx0 = fmaxf(mx0, fmaxf(sacc[j][0], sacc[j][1]));
        mx1 = fmaxf(mx1, fmaxf(sacc[j][2], sacc[j][3]));
    }
    mx0 = fmaxf(mx0, __shfl_xor_sync(0xffffffffu, mx0, 1));
    mx0 = fmaxf(mx0, __shfl_xor_sync(0xffffffffu, mx0, 2));
    mx1 = fmaxf(mx1, __shfl_xor_sync(0xffffffffu, mx1, 1));
    mx1 = fmaxf(mx1, __shfl_xor_sync(0xffffffffu, mx1, 2));

    float sum0 = 0.f, sum1 = 0.f;
#pragma unroll
    for (int j = 0; j < 8; j++) {
        sacc[j][0] = __expf(sacc[j][0] - mx0);
        sacc[j][1] = __expf(sacc[j][1] - mx0);
        sacc[j][2] = __expf(sacc[j][2] - mx1);
        sacc[j][3] = __expf(sacc[j][3] - mx1);
        sum0 += sacc[j][0] + sacc[j][1];
        sum1 += sacc[j][2] + sacc[j][3];
    }
    sum0 += __shfl_xor_sync(0xffffffffu, sum0, 1);
    sum0 += __shfl_xor_sync(0xffffffffu, sum0, 2);
    sum1 += __shfl_xor_sync(0xffffffffu, sum1, 1);
    sum1 += __shfl_xor_sync(0xffffffffu, sum1, 2);
    const float inv0 = 1.f / sum0;
    const float inv1 = 1.f / sum1;

    // Repack P (unnormalized) into A-fragments, hi/lo bf16.
    // a0=(r gid, k 2tig), a1=(r gid+8, k 2tig), a2=(r gid, k 8+2tig), a3=(r gid+8,...)
    uint32_t ph[4][4], pl[4][4];
#pragma unroll
    for (int kc = 0; kc < 4; kc++) {
        const int t0 = 2 * kc, t1 = 2 * kc + 1;
        ph[kc][0] = packsplit(sacc[t0][0], sacc[t0][1], pl[kc][0]);
        ph[kc][1] = packsplit(sacc[t0][2], sacc[t0][3], pl[kc][1]);
        ph[kc][2] = packsplit(sacc[t1][0], sacc[t1][1], pl[kc][2]);
        ph[kc][3] = packsplit(sacc[t1][2], sacc[t1][3], pl[kc][3]);
    }

    // O = P V (+ emulation): 4 d8-tiles, 4 k-chunks of 16.
    float oacc[4][4];
#pragma unroll
    for (int jd = 0; jd < 4; jd++)
#pragma unroll
        for (int t = 0; t < 4; t++) oacc[jd][t] = 0.f;

    {
        const int vrow = lane & 15;
#pragma unroll
        for (int kc = 0; kc < 4; kc++)
#pragma unroll
            for (int jd = 0; jd < 4; jd++) {
                uint32_t vh[2], vl[2];
                ldm_x2t(vh, smem_u32(&sVh[16 * kc + vrow][jd * 8]));
                ldm_x2t(vl, smem_u32(&sVl[16 * kc + vrow][jd * 8]));
                mma16816(oacc[jd], ph[kc], vh[0], vh[1]);
                mma16816(oacc[jd], pl[kc], vh[0], vh[1]);
                mma16816(oacc[jd], ph[kc], vl[0], vl[1]);
            }
    }

    // Epilogue: normalize, optionally add LePE, split to bf16 hi/lo.
#pragma unroll
    for (int jd = 0; jd < 4; jd++) {
        float x0 = oacc[jd][0] * inv0, x1 = oacc[jd][1] * inv0;
        float y0 = oacc[jd][2] * inv1, y1 = oacc[jd][3] * inv1;
        const size_t o0 = base + (size_t)r0 * row_stride + jd * 8 + tig * 2;
        const size_t o1 = base + (size_t)r1 * row_stride + jd * 8 + tig * 2;
        if (FUSE) {
            const float2 lp0 = *(const float2*)(lepe + o0);
            const float2 lp1 = *(const float2*)(lepe + o1);
            x0 += lp0.x; x1 += lp0.y;
            y0 += lp1.x; y1 += lp1.y;
        }
        uint32_t lo;
        uint32_t hi = packsplit(x0, x1, lo);
        *(uint32_t*)(Ohi + o0) = hi;
        *(uint32_t*)(Olo + o0) = lo;
        hi = packsplit(y0, y1, lo);
        *(uint32_t*)(Ohi + o1) = hi;
        *(uint32_t*)(Olo + o1) = lo;
    }
}

// ---------------------------------------------------------------------------
extern "C" void kernel_launch(void* const* d_in, const int* in_sizes, int n_in,
                              void* d_out, int out_size)
{
    const float* x      = (const float*)d_in[0];
    const float* mask_h = (const float*)d_in[1];
    const float* mask_w = (const float*)d_in[2];
    const float* Wq = (const float*)d_in[3];
    const float* bq = (const float*)d_in[4];
    const float* Wk = (const float*)d_in[5];
    const float* bk = (const float*)d_in[6];
    const float* Wv = (const float*)d_in[7];
    const float* bv = (const float*)d_in[8];
    const float* Wl = (const float*)d_in[9];
    const float* bl = (const float*)d_in[10];
    const float* Wo = (const float*)d_in[11];
    const float* bo = (const float*)d_in[12];
    float* out = (float*)d_out;

    float *v, *lepe;
    __nv_bfloat16 *qhi, *qlo, *khi, *klo, *vhi, *vlo, *v1hi, *v1lo;
    __nv_bfloat16 *ahi, *alo, *whi, *wlo;
    cudaGetSymbolAddress((void**)&v,    g_v);
    cudaGetSymbolAddress((void**)&lepe, g_lepe);
    cudaGetSymbolAddress((void**)&qhi,  g_qhi);
    cudaGetSymbolAddress((void**)&qlo,  g_qlo);
    cudaGetSymbolAddress((void**)&khi,  g_khi);
    cudaGetSymbolAddress((void**)&klo,  g_klo);
    cudaGetSymbolAddress((void**)&vhi,  g_vhi);
    cudaGetSymbolAddress((void**)&vlo,  g_vlo);
    cudaGetSymbolAddress((void**)&v1hi, g_v1hi);
    cudaGetSymbolAddress((void**)&v1lo, g_v1lo);
    cudaGetSymbolAddress((void**)&ahi,  g_ahi);
    cudaGetSymbolAddress((void**)&alo,  g_alo);
    cudaGetSymbolAddress((void**)&whi,  g_whi);
    cudaGetSymbolAddress((void**)&wlo,  g_wlo);

    static int smem_set = 0;
    if (!smem_set) {
        cudaFuncSetAttribute(gemm_hmma,
                             cudaFuncAttributeMaxDynamicSharedMemorySize,
                             GEMM_SMEM);
        smem_set = 1;
    }

    const float scaling = 0.17677669529663687f;  // 32^-0.5

    // Splits (x -> ahi/alo, consumed by QKV GEMM then reused for attn output)
    split_kernel<<<ELEMS / 4 / 256, 256>>>(x, ahi, alo, ELEMS / 4);
    split_w_kernel<<<dim3(64, 4), 256>>>(Wq, Wk, Wv, Wo, whi, wlo);

    // Fused QKV projection: emits q/k/v as bf16 hi/lo; v also fp32 (for LePE).
    gemm_hmma<<<dim3(1, 256, 3), 512, GEMM_SMEM>>>(
        ahi, alo, whi, wlo, bq, bk, bv,
        qhi, qlo, khi, klo, vhi, vlo, v, nullptr,
        1.0f, scaling, 1.0f);

    lepe_kernel<<<ELEMS / 4 / 256, 256>>>(v, Wl, bl, lepe);

    dim3 attn_grid(8, 64, 8);
    // Width-axis attention -> v1 (bf16 hi/lo)
    attn_hmma<false><<<attn_grid, 128>>>(qhi, qlo, khi, klo, vhi, vlo,
                                         mask_w, nullptr, v1hi, v1lo,
                                         /*y_stride=*/64 * 256, /*row_stride=*/256);
    // Height-axis attention + LePE add + hi/lo split -> out-proj input
    attn_hmma<true><<<attn_grid, 128>>>(qhi, qlo, khi, klo, v1hi, v1lo,
                                        mask_h, lepe, ahi, alo,
                                        /*y_stride=*/256, /*row_stride=*/64 * 256);

    // Output projection (fp32 out)
    gemm_hmma<<<dim3(1, 256, 1), 512, GEMM_SMEM>>>(
        ahi, alo, whi + 3 * 65536, wlo + 3 * 65536, bo, bo, bo,
        nullptr, nullptr, nullptr, nullptr, nullptr, nullptr, nullptr, out,
        1.0f, 1.0f, 1.0f);
}